// round 14
// baseline (speedup 1.0000x reference)
#include <cuda_runtime.h>
#include <math.h>

#define NB      32
#define SAMPLES 5000u
#define HW      (512 * 1024)
#define TOTAL   (NB * 5000)             // 160000 pairs
#define K       5                        // pairs per thread
#define NTHR    (TOTAL / K)              // 32000 threads
#define THREADS 256
#define BLOCKS  (NTHR / THREADS)         // 125 exactly
#define SIGMA   0.03f
#define EPS     1e-6f

// zero-initialized at load; reset by last block each call (graph-safe)
__device__ float        g_acc[2];        // [0]=loss sum, [1]=valid count
__device__ unsigned int g_count;

__global__ void __launch_bounds__(THREADS) rl_fused11_kernel(
    const float* __restrict__ pred,
    const float* __restrict__ targ,
    const int*   __restrict__ mask,      // bool upcast to int32 by harness
    const int*   __restrict__ idxA,
    const int*   __restrict__ idxB,
    float*       __restrict__ out)
{
    unsigned t = blockIdx.x * blockDim.x + threadIdx.x;   // < NTHR always

    // 32-bit addressing (max offset 16.8M < 2^31)
    int gA[K], gB[K];
    #pragma unroll
    for (int j = 0; j < K; j++) {
        unsigned pair = t + (unsigned)j * (unsigned)NTHR;  // coalesced
        int base = (int)(pair / SAMPLES) * HW;
        gA[j] = base + idxA[pair];
        gB[j] = base + idxB[pair];
    }

    // phase A: 2K independent mask gathers, all in flight together (MLP=10)
    int mA[K], mB[K];
    #pragma unroll
    for (int j = 0; j < K; j++) {
        mA[j] = mask[gA[j]];
        mB[j] = mask[gB[j]];
    }

    bool cm[K];
    #pragma unroll
    for (int j = 0; j < K; j++) cm[j] = (mA[j] != 0) && (mB[j] != 0);

    // phase B: conditional t/p gathers, all batched (predicated LDGs)
    float tA[K], tB[K], pA[K], pB[K];
    #pragma unroll
    for (int j = 0; j < K; j++) {
        tA[j] = 1.0f; tB[j] = 1.0f; pA[j] = 0.0f; pB[j] = 0.0f;
        if (cm[j]) {
            tA[j] = targ[gA[j]];
            tB[j] = targ[gB[j]];
            pA[j] = pred[gA[j]];
            pB[j] = pred[gB[j]];
        }
    }

    // compute — division-free threshold tests:
    //   ratio <  hi  <=>  tA <  hi*(tB+EPS)   (tB+EPS > 0 always)
    //   ratio >  lo  <=>  tA >  lo*(tB+EPS)
    float loss = 0.0f, valid = 0.0f;
    const float hi = 1.0f + SIGMA;
    const float lo = 1.0f / (1.0f + SIGMA);
    #pragma unroll
    for (int j = 0; j < K; j++) {
        if (cm[j]) {
            valid += 1.0f;
            float denom = tB[j] + EPS;
            float thi = hi * denom;
            float tlo = lo * denom;
            if (tA[j] < thi && tA[j] > tlo) {
                float d = pA[j] - pB[j];
                loss += d * d;                        // equal branch (ALPHA=1)
            } else {
                float label = (tA[j] >= thi) ? 1.0f : -1.0f;
                float x = (pB[j] - pA[j]) * label;
                loss += (x > 20.0f) ? x : log1pf(__expf(x));
            }
        }
    }

    // --- block reduction of (loss, valid) ---
    #pragma unroll
    for (int off = 16; off > 0; off >>= 1) {
        loss  += __shfl_down_sync(0xffffffffu, loss,  off);
        valid += __shfl_down_sync(0xffffffffu, valid, off);
    }

    __shared__ float s_loss[8], s_valid[8];
    __shared__ bool  s_last;
    int lane = threadIdx.x & 31;
    int wid  = threadIdx.x >> 5;
    if (lane == 0) {
        s_loss[wid]  = loss;
        s_valid[wid] = valid;
    }
    __syncthreads();

    if (wid == 0) {
        loss  = (lane < (THREADS / 32)) ? s_loss[lane]  : 0.0f;
        valid = (lane < (THREADS / 32)) ? s_valid[lane] : 0.0f;
        #pragma unroll
        for (int off = 4; off > 0; off >>= 1) {
            loss  += __shfl_down_sync(0xffffffffu, loss,  off);
            valid += __shfl_down_sync(0xffffffffu, valid, off);
        }
        if (lane == 0) {
            atomicAdd(&g_acc[0], loss);
            atomicAdd(&g_acc[1], valid);
            __threadfence();
            unsigned ticket = atomicAdd(&g_count, 1u);
            s_last = (ticket == (unsigned)(gridDim.x - 1));
        }
    }
    __syncthreads();

    // last block finalizes and resets state for next graph replay
    if (s_last && threadIdx.x == 0) {
        float l = g_acc[0], v = g_acc[1];
        out[0] = l / (v + EPS);           // ALPHA = LOSS_WEIGHT = 1
        g_acc[0] = 0.0f;
        g_acc[1] = 0.0f;
        __threadfence();
        g_count = 0u;
    }
}

extern "C" void kernel_launch(void* const* d_in, const int* in_sizes, int n_in,
                              void* d_out, int out_size)
{
    const float* pred = (const float*)d_in[0];
    const float* targ = (const float*)d_in[1];
    const int*   mask = (const int*)d_in[2];
    const int*   idxA = (const int*)d_in[3];
    const int*   idxB = (const int*)d_in[4];
    float* out = (float*)d_out;

    rl_fused11_kernel<<<BLOCKS, THREADS>>>(pred, targ, mask, idxA, idxB, out);
}

// round 15
// speedup vs baseline: 1.0029x; 1.0029x over previous
#include <cuda_runtime.h>
#include <math.h>

#define NB      32
#define SAMPLES 5000u
#define HW      (512 * 1024)
#define TOTAL   (NB * 5000)             // 160000 pairs
#define K       5                        // pairs per thread
#define NTHR    (TOTAL / K)              // 32000 threads
#define THREADS 256
#define BLOCKS  (NTHR / THREADS)         // 125 exactly
#define SIGMA   0.03f
#define EPS     1e-6f

// zero-initialized at load; reset by last block each call (graph-safe)
__device__ float        g_acc[2];        // [0]=loss sum, [1]=valid count
__device__ unsigned int g_count;

__global__ void __launch_bounds__(THREADS) rl_fused12_kernel(
    const float* __restrict__ pred,
    const float* __restrict__ targ,
    const int*   __restrict__ mask,      // bool upcast to int32 by harness
    const int*   __restrict__ idxA,
    const int*   __restrict__ idxB,
    float*       __restrict__ out)
{
    unsigned t = blockIdx.x * blockDim.x + threadIdx.x;   // < NTHR always

    // 32-bit addressing (max offset 16.8M < 2^31)
    int gA[K], gB[K];
    #pragma unroll
    for (int j = 0; j < K; j++) {
        unsigned pair = t + (unsigned)j * (unsigned)NTHR;  // coalesced
        int base = (int)(pair / SAMPLES) * HW;
        gA[j] = base + idxA[pair];
        gB[j] = base + idxB[pair];
    }

    // phase A1: K independent mA gathers (MLP=5)
    int mA[K];
    #pragma unroll
    for (int j = 0; j < K; j++) mA[j] = mask[gA[j]];

    // phase A2: mB only where mA set (~50%) — cuts mask gathers 25%
    int mB[K];
    #pragma unroll
    for (int j = 0; j < K; j++) {
        mB[j] = 0;
        if (mA[j]) mB[j] = mask[gB[j]];
    }

    bool cm[K];
    #pragma unroll
    for (int j = 0; j < K; j++) cm[j] = (mB[j] != 0);   // implies mA set

    // phase B: conditional t/p gathers, all batched (predicated LDGs)
    float tA[K], tB[K], pA[K], pB[K];
    #pragma unroll
    for (int j = 0; j < K; j++) {
        tA[j] = 1.0f; tB[j] = 1.0f; pA[j] = 0.0f; pB[j] = 0.0f;
        if (cm[j]) {
            tA[j] = targ[gA[j]];
            tB[j] = targ[gB[j]];
            pA[j] = pred[gA[j]];
            pB[j] = pred[gB[j]];
        }
    }

    // compute — division-free threshold tests (tB+EPS > 0 always)
    float loss = 0.0f, valid = 0.0f;
    const float hi = 1.0f + SIGMA;
    const float lo = 1.0f / (1.0f + SIGMA);
    #pragma unroll
    for (int j = 0; j < K; j++) {
        if (cm[j]) {
            valid += 1.0f;
            float denom = tB[j] + EPS;
            float thi = hi * denom;
            float tlo = lo * denom;
            if (tA[j] < thi && tA[j] > tlo) {
                float d = pA[j] - pB[j];
                loss += d * d;                        // equal branch (ALPHA=1)
            } else {
                float label = (tA[j] >= thi) ? 1.0f : -1.0f;
                float x = (pB[j] - pA[j]) * label;
                loss += (x > 20.0f) ? x : log1pf(__expf(x));
            }
        }
    }

    // --- block reduction of (loss, valid) ---
    #pragma unroll
    for (int off = 16; off > 0; off >>= 1) {
        loss  += __shfl_down_sync(0xffffffffu, loss,  off);
        valid += __shfl_down_sync(0xffffffffu, valid, off);
    }

    __shared__ float s_loss[8], s_valid[8];
    __shared__ bool  s_last;
    int lane = threadIdx.x & 31;
    int wid  = threadIdx.x >> 5;
    if (lane == 0) {
        s_loss[wid]  = loss;
        s_valid[wid] = valid;
    }
    __syncthreads();

    if (wid == 0) {
        loss  = (lane < (THREADS / 32)) ? s_loss[lane]  : 0.0f;
        valid = (lane < (THREADS / 32)) ? s_valid[lane] : 0.0f;
        #pragma unroll
        for (int off = 4; off > 0; off >>= 1) {
            loss  += __shfl_down_sync(0xffffffffu, loss,  off);
            valid += __shfl_down_sync(0xffffffffu, valid, off);
        }
        if (lane == 0) {
            atomicAdd(&g_acc[0], loss);
            atomicAdd(&g_acc[1], valid);
            __threadfence();
            unsigned ticket = atomicAdd(&g_count, 1u);
            s_last = (ticket == (unsigned)(gridDim.x - 1));
        }
    }
    __syncthreads();

    // last block finalizes and resets state for next graph replay
    if (s_last && threadIdx.x == 0) {
        float l = g_acc[0], v = g_acc[1];
        out[0] = l / (v + EPS);           // ALPHA = LOSS_WEIGHT = 1
        g_acc[0] = 0.0f;
        g_acc[1] = 0.0f;
        __threadfence();
        g_count = 0u;
    }
}

extern "C" void kernel_launch(void* const* d_in, const int* in_sizes, int n_in,
                              void* d_out, int out_size)
{
    const float* pred = (const float*)d_in[0];
    const float* targ = (const float*)d_in[1];
    const int*   mask = (const int*)d_in[2];
    const int*   idxA = (const int*)d_in[3];
    const int*   idxB = (const int*)d_in[4];
    float* out = (float*)d_out;

    rl_fused12_kernel<<<BLOCKS, THREADS>>>(pred, targ, mask, idxA, idxB, out);
}

// round 16
// speedup vs baseline: 1.0299x; 1.0269x over previous
#include <cuda_runtime.h>
#include <math.h>

#define NB      32
#define SAMPLES 5000u
#define HW      (512 * 1024)
#define TOTAL   (NB * 5000)             // 160000 pairs
#define K       5                        // pairs per thread
#define NTHR    (TOTAL / K)              // 32000 threads
#define THREADS 256
#define BLOCKS  (NTHR / THREADS)         // 125 exactly
#define SIGMA   0.03f
#define EPS     1e-6f

// zero-initialized at load; reset by last block each call (graph-safe)
__device__ float        g_acc[2];        // [0]=loss sum, [1]=valid count
__device__ unsigned int g_count;

__global__ void __launch_bounds__(THREADS) rl_final_kernel(
    const float* __restrict__ pred,
    const float* __restrict__ targ,
    const int*   __restrict__ mask,      // bool upcast to int32 by harness
    const int*   __restrict__ idxA,
    const int*   __restrict__ idxB,
    float*       __restrict__ out)
{
    unsigned t = blockIdx.x * blockDim.x + threadIdx.x;   // < NTHR always

    // 32-bit addressing (max offset 16.8M < 2^31)
    int gA[K], gB[K];
    #pragma unroll
    for (int j = 0; j < K; j++) {
        unsigned pair = t + (unsigned)j * (unsigned)NTHR;  // coalesced
        int base = (int)(pair / SAMPLES) * HW;
        gA[j] = base + idxA[pair];
        gB[j] = base + idxB[pair];
    }

    // phase A1: K independent mA gathers (MLP=5)
    int mA[K];
    #pragma unroll
    for (int j = 0; j < K; j++) mA[j] = mask[gA[j]];

    // phase A2: mB only where mA set (~50%) — cuts mask gathers 25%
    int mB[K];
    #pragma unroll
    for (int j = 0; j < K; j++) {
        mB[j] = 0;
        if (mA[j]) mB[j] = mask[gB[j]];
    }

    bool cm[K];
    #pragma unroll
    for (int j = 0; j < K; j++) cm[j] = (mB[j] != 0);   // implies mA set

    // phase B: conditional t/p gathers, all batched (predicated LDGs)
    float tA[K], tB[K], pA[K], pB[K];
    #pragma unroll
    for (int j = 0; j < K; j++) {
        tA[j] = 1.0f; tB[j] = 1.0f; pA[j] = 0.0f; pB[j] = 0.0f;
        if (cm[j]) {
            tA[j] = targ[gA[j]];
            tB[j] = targ[gB[j]];
            pA[j] = pred[gA[j]];
            pB[j] = pred[gB[j]];
        }
    }

    // compute — division-free threshold tests (tB+EPS > 0 always):
    //   ratio < hi  <=>  tA < hi*(tB+EPS);   ratio > lo  <=>  tA > lo*(tB+EPS)
    float loss = 0.0f, valid = 0.0f;
    const float hi = 1.0f + SIGMA;
    const float lo = 1.0f / (1.0f + SIGMA);
    #pragma unroll
    for (int j = 0; j < K; j++) {
        if (cm[j]) {
            valid += 1.0f;
            float denom = tB[j] + EPS;
            float thi = hi * denom;
            float tlo = lo * denom;
            if (tA[j] < thi && tA[j] > tlo) {
                float d = pA[j] - pB[j];
                loss += d * d;                        // equal branch (ALPHA=1)
            } else {
                float label = (tA[j] >= thi) ? 1.0f : -1.0f;
                float x = (pB[j] - pA[j]) * label;
                loss += (x > 20.0f) ? x : log1pf(__expf(x));
            }
        }
    }

    // --- block reduction of (loss, valid) ---
    #pragma unroll
    for (int off = 16; off > 0; off >>= 1) {
        loss  += __shfl_down_sync(0xffffffffu, loss,  off);
        valid += __shfl_down_sync(0xffffffffu, valid, off);
    }

    __shared__ float s_loss[8], s_valid[8];
    __shared__ bool  s_last;
    int lane = threadIdx.x & 31;
    int wid  = threadIdx.x >> 5;
    if (lane == 0) {
        s_loss[wid]  = loss;
        s_valid[wid] = valid;
    }
    __syncthreads();

    if (wid == 0) {
        loss  = (lane < (THREADS / 32)) ? s_loss[lane]  : 0.0f;
        valid = (lane < (THREADS / 32)) ? s_valid[lane] : 0.0f;
        #pragma unroll
        for (int off = 4; off > 0; off >>= 1) {
            loss  += __shfl_down_sync(0xffffffffu, loss,  off);
            valid += __shfl_down_sync(0xffffffffu, valid, off);
        }
        if (lane == 0) {
            atomicAdd(&g_acc[0], loss);
            atomicAdd(&g_acc[1], valid);
            __threadfence();
            unsigned ticket = atomicAdd(&g_count, 1u);
            s_last = (ticket == (unsigned)(gridDim.x - 1));
        }
    }
    __syncthreads();

    // last block finalizes and resets state for next graph replay
    if (s_last && threadIdx.x == 0) {
        float l = g_acc[0], v = g_acc[1];
        out[0] = l / (v + EPS);           // ALPHA = LOSS_WEIGHT = 1
        g_acc[0] = 0.0f;
        g_acc[1] = 0.0f;
        __threadfence();
        g_count = 0u;
    }
}

extern "C" void kernel_launch(void* const* d_in, const int* in_sizes, int n_in,
                              void* d_out, int out_size)
{
    const float* pred = (const float*)d_in[0];
    const float* targ = (const float*)d_in[1];
    const int*   mask = (const int*)d_in[2];
    const int*   idxA = (const int*)d_in[3];
    const int*   idxB = (const int*)d_in[4];
    float* out = (float*)d_out;

    rl_final_kernel<<<BLOCKS, THREADS>>>(pred, targ, mask, idxA, idxB, out);
}